// round 13
// baseline (speedup 1.0000x reference)
#include <cuda_runtime.h>
#include <cuda_fp16.h>
#include <cstdint>
#include <cstddef>

// Problem dims
#define M_DIM 4096   // batch
#define N_DIM 2048   // out features
#define K_DIM 2048   // in features

// ---------------------------------------------------------------------------
// Scratch: fp16 copies of x and w. Single-product fp16 GEMM, fp32 accumulate.
// Measured R10/R12: rel_err 2.94e-4 (gate 1e-3).
// ---------------------------------------------------------------------------
__device__ __align__(16) __half g_xh[(size_t)M_DIM * K_DIM];
__device__ __align__(16) __half g_wh[(size_t)N_DIM * K_DIM];

// ---------------------------------------------------------------------------
// Helpers (baseline sm_103 ISA: cp.async, ldmatrix, mma.sync f16)
// ---------------------------------------------------------------------------
__device__ __forceinline__ uint32_t smem_u32(const void* p) {
    uint32_t a;
    asm("{ .reg .u64 t; cvta.to.shared.u64 t, %1; cvt.u32.u64 %0, t; }"
        : "=r"(a) : "l"(p));
    return a;
}

__device__ __forceinline__ void cp_async16(uint32_t saddr, const void* gaddr) {
    asm volatile("cp.async.cg.shared.global [%0], [%1], 16;"
                 :: "r"(saddr), "l"(gaddr) : "memory");
}

__device__ __forceinline__ void ldsm4(uint32_t* r, uint32_t addr) {
    asm volatile("ldmatrix.sync.aligned.m8n8.x4.shared.b16 {%0,%1,%2,%3}, [%4];"
                 : "=r"(r[0]), "=r"(r[1]), "=r"(r[2]), "=r"(r[3])
                 : "r"(addr));
}

__device__ __forceinline__ void mma_f16(float* d, const uint32_t* a,
                                        const uint32_t b0, const uint32_t b1) {
    asm volatile(
        "mma.sync.aligned.m16n8k16.row.col.f32.f16.f16.f32 "
        "{%0,%1,%2,%3}, {%4,%5,%6,%7}, {%8,%9}, {%0,%1,%2,%3};"
        : "+f"(d[0]), "+f"(d[1]), "+f"(d[2]), "+f"(d[3])
        : "r"(a[0]), "r"(a[1]), "r"(a[2]), "r"(a[3]), "r"(b0), "r"(b1));
}

// ---------------------------------------------------------------------------
// Fused convert kernel: fp32 -> fp16, 16 elems/thread (MLP=4).
// ---------------------------------------------------------------------------
static constexpr size_t XN = (size_t)M_DIM * K_DIM;          // 8388608
static constexpr size_t WN = (size_t)N_DIM * K_DIM;          // 4194304
static constexpr int CVT_THREADS = (int)((XN + WN) / 16);    // 786432

union H8 { __half h[8]; uint4 u; };

__global__ void __launch_bounds__(256)
cvt_kernel(const float* __restrict__ x, const float* __restrict__ w) {
    size_t t = (size_t)blockIdx.x * blockDim.x + threadIdx.x;
    size_t base = t * 16;
    const float* src;
    __half* dst;
    if (base < XN) { src = x; dst = g_xh; }
    else           { src = w - XN; dst = g_wh - XN; }   // flat offset math

    float4 v[4];
#pragma unroll
    for (int j = 0; j < 4; j++)
        v[j] = *reinterpret_cast<const float4*>(src + base + j * 4);

#pragma unroll
    for (int p = 0; p < 2; p++) {
        H8 H;
        H.h[0] = __float2half_rn(v[p * 2].x);
        H.h[1] = __float2half_rn(v[p * 2].y);
        H.h[2] = __float2half_rn(v[p * 2].z);
        H.h[3] = __float2half_rn(v[p * 2].w);
        H.h[4] = __float2half_rn(v[p * 2 + 1].x);
        H.h[5] = __float2half_rn(v[p * 2 + 1].y);
        H.h[6] = __float2half_rn(v[p * 2 + 1].z);
        H.h[7] = __float2half_rn(v[p * 2 + 1].w);
        *reinterpret_cast<uint4*>(dst + base + p * 8) = H.u;
    }
}

// ---------------------------------------------------------------------------
// GEMM: 128(M) x 64(N) CTA tile, 4 warps, warp tile 64x32 (2m x 2n).
// Crossbar traffic per kt: reads A 16KB (x2 redundancy) + B 8KB (x2) +
// writes 12KB  ->  ~280 cyc vs tensor 256 cyc: pipes balanced (R12 had
// B x4 redundancy -> L1-bound at 50.6%).
// BK=32, 4-stage cp.async pipeline, 1024 CTAs (balance ~1%), occ 3.
// ---------------------------------------------------------------------------
static constexpr int BK      = 32;               // fp16 elements per K-chunk
static constexpr int KT      = K_DIM / BK;       // 64 iterations
static constexpr int ROW_B   = BK * 2 + 16;      // 80B padded row (conflict-free ldsm)
static constexpr int TILE_A  = 128 * ROW_B;      // 10240 B (A: 128 rows)
static constexpr int TILE_BB = 64 * ROW_B;       // 5120 B  (B: 64 rows)
static constexpr int STAGE_B = TILE_A + TILE_BB; // 15360 B
static constexpr int NSTAGE  = 4;
static constexpr int SMEM_DYN = NSTAGE * STAGE_B + 1024;   // ~62.5 KB

__global__ void __launch_bounds__(128, 3)
gemm_kernel(const float* __restrict__ bias, float* __restrict__ out) {
    extern __shared__ char smem_raw[];
    const uint32_t dynbase = (smem_u32(smem_raw) + 1023u) & ~1023u;

    const int tid = threadIdx.x;
    const int wid = tid >> 5;          // 0..3
    const int lid = tid & 31;
    const int bn  = blockIdx.x;        // 0..31 (64-wide N tiles)
    const int bm  = blockIdx.y;        // 0..31 (128-high M tiles)

    const int m0 = (wid & 1) * 64;     // warp m-offset (64-row half)
    const int n0 = (wid >> 1) * 32;    // warp n-offset (32-col half)

    const __half* xh = g_xh + (size_t)bm * 128 * K_DIM;
    const __half* wh = g_wh + (size_t)bn * 64 * K_DIM;

    // cp.async geometry (128 threads):
    //   A tile: 512 chunks of 16B (row=c/4, c4=c%4), 4 per thread.
    //   B tile: 256 chunks of 16B (row=c/4, c4=c%4), 2 per thread.
    int rA[4], cA[4];
    uint32_t sA[4];
#pragma unroll
    for (int h = 0; h < 4; h++) {
        int ci = h * 128 + tid;
        rA[h] = ci >> 2;
        cA[h] = (ci & 3) * 8;
        sA[h] = (uint32_t)(rA[h] * ROW_B + (ci & 3) * 16);
    }
    int rB[2], cB[2];
    uint32_t sB[2];
#pragma unroll
    for (int h = 0; h < 2; h++) {
        int ci = h * 128 + tid;
        rB[h] = ci >> 2;
        cB[h] = (ci & 3) * 8;
        sB[h] = (uint32_t)(rB[h] * ROW_B + (ci & 3) * 16);
    }

    auto load_stage = [&](int s, int kt) {
        const int k0 = kt * BK;
        const uint32_t sb = dynbase + s * STAGE_B;
#pragma unroll
        for (int h = 0; h < 4; h++)
            cp_async16(sb + sA[h], xh + (size_t)rA[h] * K_DIM + k0 + cA[h]);
#pragma unroll
        for (int h = 0; h < 2; h++)
            cp_async16(sb + TILE_A + sB[h], wh + (size_t)rB[h] * K_DIM + k0 + cB[h]);
        asm volatile("cp.async.commit_group;" ::: "memory");
    };

    // ldmatrix per-lane base offsets (bytes) within a tile
    const uint32_t lrow = (uint32_t)(lid & 15);
    const uint32_t lchk = (uint32_t)(lid >> 4) * 16;
    const uint32_t aoff = (uint32_t)(m0 + lrow) * ROW_B + lchk;
    const uint32_t boff = (uint32_t)(n0 + lrow) * ROW_B + lchk;

    float acc[4][4][4];
#pragma unroll
    for (int mt = 0; mt < 4; mt++)
#pragma unroll
        for (int nt = 0; nt < 4; nt++)
#pragma unroll
            for (int q = 0; q < 4; q++) acc[mt][nt][q] = 0.0f;

    // Prologue: fill 3 stages
    load_stage(0, 0);
    load_stage(1, 1);
    load_stage(2, 2);

#pragma unroll 1
    for (int kt = 0; kt < KT; kt++) {
        asm volatile("cp.async.wait_group 2;" ::: "memory");
        __syncthreads();

        // Refill stage (kt+3); its slot was consumed at iter kt-1 (guarded by
        // the barrier above). Always commit so wait_group accounting stays 1:1.
        if (kt + 3 < KT) load_stage((kt + 3) & 3, kt + 3);
        else asm volatile("cp.async.commit_group;" ::: "memory");

        const uint32_t sba = dynbase + (kt & 3) * STAGE_B;
        const uint32_t sbb = sba + TILE_A;

#pragma unroll
        for (int ks = 0; ks < 2; ks++) {
            const uint32_t kb = (uint32_t)(ks * 32);   // 16 halves = 32B

            uint32_t A[4][4];
#pragma unroll
            for (int mt = 0; mt < 4; mt++)
                ldsm4(A[mt], sba + aoff + mt * (16 * ROW_B) + kb);

#pragma unroll
            for (int nt2 = 0; nt2 < 2; nt2++) {
                uint32_t r[4];
                ldsm4(r, sbb + boff + nt2 * (16 * ROW_B) + kb);
#pragma unroll
                for (int mt = 0; mt < 4; mt++) {
                    mma_f16(acc[mt][nt2 * 2],     A[mt], r[0], r[2]);
                    mma_f16(acc[mt][nt2 * 2 + 1], A[mt], r[1], r[3]);
                }
            }
        }
    }

    // Epilogue: add bias, store float2 per fragment half.
    const int cq = (lid & 3) * 2;       // col pair within n8 tile
    const int cr = lid >> 2;            // row within m16 tile (0..7)
    const float* bp = bias + bn * 64 + n0;

    float2 bv[4];
#pragma unroll
    for (int nt = 0; nt < 4; nt++)
        bv[nt] = *reinterpret_cast<const float2*>(bp + nt * 8 + cq);

#pragma unroll
    for (int mt = 0; mt < 4; mt++) {
        const int row_g = bm * 128 + m0 + mt * 16 + cr;
        float* orow = out + (size_t)row_g * N_DIM + bn * 64 + n0;
#pragma unroll
        for (int nt = 0; nt < 4; nt++) {
            float2 v0, v1;
            v0.x = acc[mt][nt][0] + bv[nt].x;
            v0.y = acc[mt][nt][1] + bv[nt].y;
            v1.x = acc[mt][nt][2] + bv[nt].x;
            v1.y = acc[mt][nt][3] + bv[nt].y;
            *reinterpret_cast<float2*>(orow + nt * 8 + cq) = v0;
            *reinterpret_cast<float2*>(orow + (size_t)8 * N_DIM + nt * 8 + cq) = v1;
        }
    }
}

// ---------------------------------------------------------------------------
// kernel_launch: fused fp16 convert, then single-product HMMA GEMM.
// Graph-capturable (kernel launches only).
// ---------------------------------------------------------------------------
extern "C" void kernel_launch(void* const* d_in, const int* in_sizes, int n_in,
                              void* d_out, int out_size) {
    const float* x    = (const float*)d_in[0];   // [4096, 2048]
    const float* w    = (const float*)d_in[1];   // [2048, 2048]
    const float* bias = (const float*)d_in[2];   // [2048]
    float* out = (float*)d_out;                  // [4096, 2048]

    (void)in_sizes; (void)n_in; (void)out_size;

    cvt_kernel<<<CVT_THREADS / 256, 256>>>(x, w);

    static bool attr_set = false;
    if (!attr_set) {
        cudaFuncSetAttribute(gemm_kernel,
                             cudaFuncAttributeMaxDynamicSharedMemorySize, SMEM_DYN);
        attr_set = true;
    }
    dim3 grid(N_DIM / 64, M_DIM / 128);   // (32, 32) = 1024 CTAs
    gemm_kernel<<<grid, 128, SMEM_DYN>>>(bias, out);
}

// round 15
// speedup vs baseline: 1.1316x; 1.1316x over previous
#include <cuda_runtime.h>
#include <cuda_fp16.h>
#include <cstdint>
#include <cstddef>

// Problem dims
#define M_DIM 4096   // batch
#define N_DIM 2048   // out features
#define K_DIM 2048   // in features

// ---------------------------------------------------------------------------
// Scratch: fp16 copies of x and w. Single-product fp16 GEMM, fp32 accumulate.
// Measured R10/R12: rel_err 2.94e-4 (gate 1e-3).
// ---------------------------------------------------------------------------
__device__ __align__(16) __half g_xh[(size_t)M_DIM * K_DIM];
__device__ __align__(16) __half g_wh[(size_t)N_DIM * K_DIM];

// ---------------------------------------------------------------------------
// Helpers (baseline sm_103 ISA: cp.async, ldmatrix, mma.sync f16)
// ---------------------------------------------------------------------------
__device__ __forceinline__ uint32_t smem_u32(const void* p) {
    uint32_t a;
    asm("{ .reg .u64 t; cvta.to.shared.u64 t, %1; cvt.u32.u64 %0, t; }"
        : "=r"(a) : "l"(p));
    return a;
}

__device__ __forceinline__ void cp_async16(uint32_t saddr, const void* gaddr) {
    asm volatile("cp.async.cg.shared.global [%0], [%1], 16;"
                 :: "r"(saddr), "l"(gaddr) : "memory");
}

__device__ __forceinline__ void ldsm4(uint32_t* r, uint32_t addr) {
    asm volatile("ldmatrix.sync.aligned.m8n8.x4.shared.b16 {%0,%1,%2,%3}, [%4];"
                 : "=r"(r[0]), "=r"(r[1]), "=r"(r[2]), "=r"(r[3])
                 : "r"(addr));
}

__device__ __forceinline__ void mma_f16(float* d, const uint32_t* a,
                                        const uint32_t b0, const uint32_t b1) {
    asm volatile(
        "mma.sync.aligned.m16n8k16.row.col.f32.f16.f16.f32 "
        "{%0,%1,%2,%3}, {%4,%5,%6,%7}, {%8,%9}, {%0,%1,%2,%3};"
        : "+f"(d[0]), "+f"(d[1]), "+f"(d[2]), "+f"(d[3])
        : "r"(a[0]), "r"(a[1]), "r"(a[2]), "r"(a[3]), "r"(b0), "r"(b1));
}

// ---------------------------------------------------------------------------
// Fused convert kernel: fp32 -> fp16, 16 elems/thread (MLP=4).
// ---------------------------------------------------------------------------
static constexpr size_t XN = (size_t)M_DIM * K_DIM;          // 8388608
static constexpr size_t WN = (size_t)N_DIM * K_DIM;          // 4194304
static constexpr int CVT_THREADS = (int)((XN + WN) / 16);    // 786432

union H8 { __half h[8]; uint4 u; };

__global__ void __launch_bounds__(256)
cvt_kernel(const float* __restrict__ x, const float* __restrict__ w) {
    size_t t = (size_t)blockIdx.x * blockDim.x + threadIdx.x;
    size_t base = t * 16;
    const float* src;
    __half* dst;
    if (base < XN) { src = x; dst = g_xh; }
    else           { src = w - XN; dst = g_wh - XN; }   // flat offset math

    float4 v[4];
#pragma unroll
    for (int j = 0; j < 4; j++)
        v[j] = *reinterpret_cast<const float4*>(src + base + j * 4);

#pragma unroll
    for (int p = 0; p < 2; p++) {
        H8 H;
        H.h[0] = __float2half_rn(v[p * 2].x);
        H.h[1] = __float2half_rn(v[p * 2].y);
        H.h[2] = __float2half_rn(v[p * 2].z);
        H.h[3] = __float2half_rn(v[p * 2].w);
        H.h[4] = __float2half_rn(v[p * 2 + 1].x);
        H.h[5] = __float2half_rn(v[p * 2 + 1].y);
        H.h[6] = __float2half_rn(v[p * 2 + 1].z);
        H.h[7] = __float2half_rn(v[p * 2 + 1].w);
        *reinterpret_cast<uint4*>(dst + base + p * 8) = H.u;
    }
}

// ---------------------------------------------------------------------------
// GEMM: 128(M) x 64(N) CTA tile, 8 warps as 4(m) x 2(n), warp tile 32x32
// (identical to the 135us R12 layout). Change vs R12: BK 32->64 (32 mainloop
// iterations, half the barrier/wait overhead, 2x independent work per
// interval) and 3 stages (82 KB smem, still 2 CTAs/SM = 16 warps).
// R13 lesson: warp-parallelism > crossbar traffic; kernel is latency-bound.
// ---------------------------------------------------------------------------
static constexpr int BK      = 64;               // fp16 elements per K-chunk
static constexpr int KT      = K_DIM / BK;       // 32 iterations
static constexpr int ROW_B   = BK * 2 + 16;      // 144B padded row (conflict-free ldsm)
static constexpr int TILE_A  = 128 * ROW_B;      // 18432 B (A: 128 rows)
static constexpr int TILE_BB = 64 * ROW_B;       // 9216 B  (B: 64 rows)
static constexpr int STAGE_B = TILE_A + TILE_BB; // 27648 B
static constexpr int NSTAGE  = 3;
static constexpr int SMEM_DYN = NSTAGE * STAGE_B + 1024;   // ~82 KB

__global__ void __launch_bounds__(256, 2)
gemm_kernel(const float* __restrict__ bias, float* __restrict__ out) {
    extern __shared__ char smem_raw[];
    const uint32_t dynbase = (smem_u32(smem_raw) + 1023u) & ~1023u;

    const int tid = threadIdx.x;
    const int wid = tid >> 5;
    const int lid = tid & 31;
    const int bn  = blockIdx.x;        // 0..31 (64-wide N tiles)
    const int bm  = blockIdx.y;        // 0..31 (128-high M tiles)

    const int m0 = (wid & 3) * 32;     // warp m-offset in CTA tile
    const int n0 = (wid >> 2) * 32;    // warp n-offset in CTA tile

    const __half* xh = g_xh + (size_t)bm * 128 * K_DIM;
    const __half* wh = g_wh + (size_t)bn * 64 * K_DIM;

    // cp.async geometry (256 threads, BK=64 -> 128B data rows):
    //   A tile: 1024 chunks of 16B (row=c/8, c8=c%8), 4 per thread.
    //   B tile:  512 chunks of 16B (row=c/8, c8=c%8), 2 per thread.
    int rA[4], cA[4];
    uint32_t sA[4];
#pragma unroll
    for (int h = 0; h < 4; h++) {
        int ci = h * 256 + tid;
        rA[h] = ci >> 3;
        cA[h] = (ci & 7) * 8;
        sA[h] = (uint32_t)(rA[h] * ROW_B + (ci & 7) * 16);
    }
    int rB[2], cB[2];
    uint32_t sB[2];
#pragma unroll
    for (int h = 0; h < 2; h++) {
        int ci = h * 256 + tid;
        rB[h] = ci >> 3;
        cB[h] = (ci & 7) * 8;
        sB[h] = (uint32_t)(rB[h] * ROW_B + (ci & 7) * 16);
    }

    auto load_stage = [&](int s, int kt) {
        const int k0 = kt * BK;
        const uint32_t sb = dynbase + s * STAGE_B;
#pragma unroll
        for (int h = 0; h < 4; h++)
            cp_async16(sb + sA[h], xh + (size_t)rA[h] * K_DIM + k0 + cA[h]);
#pragma unroll
        for (int h = 0; h < 2; h++)
            cp_async16(sb + TILE_A + sB[h], wh + (size_t)rB[h] * K_DIM + k0 + cB[h]);
        asm volatile("cp.async.commit_group;" ::: "memory");
    };

    // ldmatrix per-lane base offsets (bytes) within a tile
    const uint32_t lrow = (uint32_t)(lid & 15);
    const uint32_t lchk = (uint32_t)(lid >> 4) * 16;
    const uint32_t aoff = (uint32_t)(m0 + lrow) * ROW_B + lchk;
    const uint32_t boff = (uint32_t)(n0 + lrow) * ROW_B + lchk;

    float acc[2][4][4];
#pragma unroll
    for (int mt = 0; mt < 2; mt++)
#pragma unroll
        for (int nt = 0; nt < 4; nt++)
#pragma unroll
            for (int q = 0; q < 4; q++) acc[mt][nt][q] = 0.0f;

    // Prologue: fill 2 of 3 stages
    load_stage(0, 0);
    load_stage(1, 1);

#pragma unroll 1
    for (int kt = 0; kt < KT; kt++) {
        // Complete stage kt (leave the newest pending group in flight).
        asm volatile("cp.async.wait_group 1;" ::: "memory");
        __syncthreads();

        // Refill stage (kt+2) mod 3; its slot was consumed at iter kt-1
        // (guarded by the barrier above). Always commit to keep accounting 1:1.
        if (kt + 2 < KT) {
            int s = kt + 2;
            s -= (s >= 3) ? 3 : 0;
            s -= (s >= 3) ? 3 : 0;   // (kt+2)%3 without div: kt<32 so two folds
            // simpler: compute below
        }
        {
            int s2 = (kt + 2) % 3;
            if (kt + 2 < KT) load_stage(s2, kt + 2);
            else asm volatile("cp.async.commit_group;" ::: "memory");
        }

        const uint32_t sba = dynbase + (kt % 3) * STAGE_B;
        const uint32_t sbb = sba + TILE_A;

#pragma unroll
        for (int ks = 0; ks < 4; ks++) {
            const uint32_t kb = (uint32_t)(ks * 32);   // 16 halves = 32B

            uint32_t A[2][4];
#pragma unroll
            for (int mt = 0; mt < 2; mt++)
                ldsm4(A[mt], sba + aoff + mt * (16 * ROW_B) + kb);

#pragma unroll
            for (int nt2 = 0; nt2 < 2; nt2++) {
                uint32_t r[4];
                ldsm4(r, sbb + boff + nt2 * (16 * ROW_B) + kb);
#pragma unroll
                for (int mt = 0; mt < 2; mt++) {
                    mma_f16(acc[mt][nt2 * 2],     A[mt], r[0], r[2]);
                    mma_f16(acc[mt][nt2 * 2 + 1], A[mt], r[1], r[3]);
                }
            }
        }
    }

    // Epilogue: add bias, store float2 per fragment half.
    const int cq = (lid & 3) * 2;       // col pair within n8 tile
    const int cr = lid >> 2;            // row within m16 tile (0..7)
    const float* bp = bias + bn * 64 + n0;

    float2 bv[4];
#pragma unroll
    for (int nt = 0; nt < 4; nt++)
        bv[nt] = *reinterpret_cast<const float2*>(bp + nt * 8 + cq);

#pragma unroll
    for (int mt = 0; mt < 2; mt++) {
        const int row_g = bm * 128 + m0 + mt * 16 + cr;
        float* orow = out + (size_t)row_g * N_DIM + bn * 64 + n0;
#pragma unroll
        for (int nt = 0; nt < 4; nt++) {
            float2 v0, v1;
            v0.x = acc[mt][nt][0] + bv[nt].x;
            v0.y = acc[mt][nt][1] + bv[nt].y;
            v1.x = acc[mt][nt][2] + bv[nt].x;
            v1.y = acc[mt][nt][3] + bv[nt].y;
            *reinterpret_cast<float2*>(orow + nt * 8 + cq) = v0;
            *reinterpret_cast<float2*>(orow + (size_t)8 * N_DIM + nt * 8 + cq) = v1;
        }
    }
}

// ---------------------------------------------------------------------------
// kernel_launch: fused fp16 convert, then single-product HMMA GEMM.
// Graph-capturable (kernel launches only).
// ---------------------------------------------------------------------------
extern "C" void kernel_launch(void* const* d_in, const int* in_sizes, int n_in,
                              void* d_out, int out_size) {
    const float* x    = (const float*)d_in[0];   // [4096, 2048]
    const float* w    = (const float*)d_in[1];   // [2048, 2048]
    const float* bias = (const float*)d_in[2];   // [2048]
    float* out = (float*)d_out;                  // [4096, 2048]

    (void)in_sizes; (void)n_in; (void)out_size;

    cvt_kernel<<<CVT_THREADS / 256, 256>>>(x, w);

    static bool attr_set = false;
    if (!attr_set) {
        cudaFuncSetAttribute(gemm_kernel,
                             cudaFuncAttributeMaxDynamicSharedMemorySize, SMEM_DYN);
        attr_set = true;
    }
    dim3 grid(N_DIM / 64, M_DIM / 128);   // (32, 32) = 1024 CTAs
    gemm_kernel<<<grid, 256, SMEM_DYN>>>(bias, out);
}